// round 1
// baseline (speedup 1.0000x reference)
#include <cuda_runtime.h>
#include <math.h>

#define BB  4
#define LL  1024
#define DD  1024
#define HH  16
#define DHH 64
#define FF  7

// ---- scratch (module-static device memory; no runtime allocation) ----
__device__ float g_Q[BB*LL*DD];
__device__ float g_K[BB*LL*DD];
__device__ float g_V[BB*LL*DD];
__device__ float g_S[(size_t)BB*HH*LL*LL];   // raw scores, 268 MB
__device__ float g_AO[BB*LL*DD];             // attn @ V, head-merged layout

// ============================================================================
// Generic register-tiled fp32 GEMM:
//   TB=true :  C[m,n] = alpha * sum_k A[m,k]*B[n,k]   (B is [N,K] row-major)
//   TB=false:  C[m,n] = alpha * sum_k A[m,k]*B[k,n]   (B is [K,N] row-major)
// Optional bias added per-column. Batched via blockIdx.z with
// offset(z) = (z/hmod)*S1 + (z%hmod)*S2 per tensor.
// ============================================================================
template<int BM,int BN,int BK,int TM,int TN,bool TB>
__global__ __launch_bounds__(256)
void sgemm_kernel(const float* __restrict__ A, const float* __restrict__ B,
                  const float* __restrict__ bias, float* __restrict__ C,
                  int K, int lda, int ldb, int ldc,
                  int hmod, int aS1, int aS2, int bS1, int bS2, int cS1, int cS2,
                  float alpha)
{
    const int z = blockIdx.z;
    const int zd = z / hmod, zm = z % hmod;
    const float* Ab = A + (size_t)zd*aS1 + (size_t)zm*aS2;
    const float* Bb = B + (size_t)zd*bS1 + (size_t)zm*bS2;
    float*       Cb = C + (size_t)zd*cS1 + (size_t)zm*cS2;

    __shared__ float As[BK][BM];
    __shared__ float Bs[BK][BN];

    const int tid = threadIdx.x;
    const int TX = BN / TN;                 // threads along n
    const int tx = tid % TX, ty = tid / TX;
    const int m0 = blockIdx.y * BM, n0 = blockIdx.x * BN;

    float acc[TM][TN];
    #pragma unroll
    for (int i = 0; i < TM; i++)
        #pragma unroll
        for (int j = 0; j < TN; j++) acc[i][j] = 0.f;

    for (int k0 = 0; k0 < K; k0 += BK) {
        // load A tile (rows m, cols k) -> As[k][m]
        #pragma unroll
        for (int t = tid; t < BM*BK/4; t += 256) {
            const int row = t / (BK/4);
            const int kq  = t % (BK/4);
            float4 v = *(const float4*)(Ab + (size_t)(m0+row)*lda + k0 + kq*4);
            As[kq*4+0][row] = v.x; As[kq*4+1][row] = v.y;
            As[kq*4+2][row] = v.z; As[kq*4+3][row] = v.w;
        }
        if (TB) {
            #pragma unroll
            for (int t = tid; t < BN*BK/4; t += 256) {
                const int row = t / (BK/4);
                const int kq  = t % (BK/4);
                float4 v = *(const float4*)(Bb + (size_t)(n0+row)*ldb + k0 + kq*4);
                Bs[kq*4+0][row] = v.x; Bs[kq*4+1][row] = v.y;
                Bs[kq*4+2][row] = v.z; Bs[kq*4+3][row] = v.w;
            }
        } else {
            #pragma unroll
            for (int t = tid; t < BN*BK/4; t += 256) {
                const int kr = t / (BN/4);
                const int nq = t % (BN/4);
                float4 v = *(const float4*)(Bb + (size_t)(k0+kr)*ldb + n0 + nq*4);
                *(float4*)&Bs[kr][nq*4] = v;
            }
        }
        __syncthreads();

        #pragma unroll
        for (int kk = 0; kk < BK; kk++) {
            float a[TM], b[TN];
            #pragma unroll
            for (int i = 0; i < TM; i++) a[i] = As[kk][ty*TM + i];
            #pragma unroll
            for (int j = 0; j < TN; j++) b[j] = Bs[kk][tx*TN + j];
            #pragma unroll
            for (int i = 0; i < TM; i++)
                #pragma unroll
                for (int j = 0; j < TN; j++)
                    acc[i][j] = fmaf(a[i], b[j], acc[i][j]);
        }
        __syncthreads();
    }

    // epilogue (vectorized stores)
    #pragma unroll
    for (int i = 0; i < TM; i++) {
        const int m = m0 + ty*TM + i;
        #pragma unroll
        for (int j = 0; j < TN; j += 4) {
            const int n = n0 + tx*TN + j;
            float4 v;
            v.x = acc[i][j+0]*alpha; v.y = acc[i][j+1]*alpha;
            v.z = acc[i][j+2]*alpha; v.w = acc[i][j+3]*alpha;
            if (bias) {
                v.x += bias[n+0]; v.y += bias[n+1];
                v.z += bias[n+2]; v.w += bias[n+3];
            }
            *(float4*)(Cb + (size_t)m*ldc + n) = v;
        }
    }
}

// ============================================================================
// Bias network + softmax. One block per (b, i). 256 threads.
// distmap[f] computed once per (b,i,j) in smem, reused for all 16 heads.
// ============================================================================
__device__ __forceinline__ float blockMax(float v, float* red) {
    #pragma unroll
    for (int o = 16; o; o >>= 1) v = fmaxf(v, __shfl_xor_sync(0xffffffffu, v, o));
    const int w = threadIdx.x >> 5, lane = threadIdx.x & 31;
    __syncthreads();
    if (lane == 0) red[w] = v;
    __syncthreads();
    float r = red[0];
    #pragma unroll
    for (int k = 1; k < 8; k++) r = fmaxf(r, red[k]);
    return r;
}

__device__ __forceinline__ float blockSum(float v, float* red) {
    #pragma unroll
    for (int o = 16; o; o >>= 1) v += __shfl_xor_sync(0xffffffffu, v, o);
    const int w = threadIdx.x >> 5, lane = threadIdx.x & 31;
    __syncthreads();
    if (lane == 0) red[w] = v;
    __syncthreads();
    float r = red[0];
    #pragma unroll
    for (int k = 1; k < 8; k++) r += red[k];
    return r;
}

__global__ __launch_bounds__(256)
void bias_softmax_kernel(const float* __restrict__ S,
                         const float* __restrict__ dq,
                         const float* __restrict__ dkt,
                         const float* __restrict__ dkb,
                         const float* __restrict__ dks,
                         const float* __restrict__ relt,
                         const float* __restrict__ relb,
                         const float* __restrict__ Ww,
                         const float* __restrict__ Wb,
                         float* __restrict__ attn)
{
    __shared__ float sDm[FF][LL];     // 28 KB
    __shared__ float sW[2][HH*FF];
    __shared__ float red[8];

    const int bi  = blockIdx.x;       // b*L + i
    const int b   = bi >> 10;
    const int i   = bi & 1023;
    const int tid = threadIdx.x;

    if (tid < HH*FF) { sW[0][tid] = Ww[tid]; sW[1][tid] = Wb[tid]; }

    const float dq0 = dq[bi*3+0], dq1 = dq[bi*3+1], dq2 = dq[bi*3+2];
    const size_t riBase = (size_t)bi * LL * 4;

    for (int j = tid; j < LL; j += 256) {
        const float* kt = dkt + ((size_t)b*LL + j)*3;
        const float* kb = dkb + ((size_t)b*LL + j)*3;
        const float* ks = dks + ((size_t)b*LL + j)*14;
        const float4 rt = *(const float4*)(relt + riBase + (size_t)j*4);
        const float4 rb = *(const float4*)(relb + riBase + (size_t)j*4);
        float top[FF] = { dq0-kt[0], dq1-kt[1], dq2-kt[2], rt.x, rt.y, rt.z, rt.w };
        float bot[FF] = { dq0-kb[0], dq1-kb[1], dq2-kb[2], rb.x, rb.y, rb.z, rb.w };
        #pragma unroll
        for (int f = 0; f < FF; f++)
            sDm[f][j] = fmaf(top[f], ks[f], bot[f]*ks[7+f]);
    }
    __syncthreads();

    for (int h = 0; h < HH; h++) {
        const float* Srow = S + (((size_t)b*HH + h)*LL + i)*LL;
        float wW[FF], wB[FF];
        #pragma unroll
        for (int f = 0; f < FF; f++) { wW[f] = sW[0][h*FF+f]; wB[f] = sW[1][h*FF+f]; }

        float vals[4];
        float mx = -1e30f;
        #pragma unroll
        for (int r = 0; r < 4; r++) {
            const int j = tid + r*256;
            float dw = 0.f, db = 0.f;
            #pragma unroll
            for (int f = 0; f < FF; f++) {
                const float d = sDm[f][j];
                dw = fmaf(d, wW[f], dw);
                db = fmaf(d, wB[f], db);
            }
            const float sp = (dw > 15.f) ? dw : log1pf(__expf(dw));
            const float sc = fmaf(Srow[j], sp, db);
            vals[r] = sc;
            mx = fmaxf(mx, sc);
        }
        mx = blockMax(mx, red);

        float sum = 0.f;
        #pragma unroll
        for (int r = 0; r < 4; r++) {
            vals[r] = __expf(vals[r] - mx);
            sum += vals[r];
        }
        sum = blockSum(sum, red);
        const float inv = 1.f / sum;

        float* Arow = attn + (((size_t)b*HH + h)*LL + i)*LL;
        #pragma unroll
        for (int r = 0; r < 4; r++)
            Arow[tid + r*256] = vals[r] * inv;
    }
}

// ============================================================================
// launcher
// ============================================================================
extern "C" void kernel_launch(void* const* d_in, const int* in_sizes, int n_in,
                              void* d_out, int out_size)
{
    const float* q    = (const float*)d_in[0];
    const float* k    = (const float*)d_in[1];
    const float* v    = (const float*)d_in[2];
    const float* dq   = (const float*)d_in[3];
    const float* dkt  = (const float*)d_in[4];
    const float* dkb  = (const float*)d_in[5];
    const float* dks  = (const float*)d_in[6];
    const float* relt = (const float*)d_in[7];
    const float* relb = (const float*)d_in[8];
    const float* W_q  = (const float*)d_in[9];
    const float* b_q  = (const float*)d_in[10];
    const float* W_k  = (const float*)d_in[11];
    const float* W_v  = (const float*)d_in[12];
    // d_in[13] = W_c : computed but unused by the reference outputs -> skipped
    const float* W_w  = (const float*)d_in[14];
    const float* W_b  = (const float*)d_in[15];
    const float* W_o  = (const float*)d_in[16];
    const float* b_o  = (const float*)d_in[17];

    float* outO = (float*)d_out;                         // [B,L,D]
    float* outA = outO + (size_t)BB*LL*DD;               // [B,H,L,L]

    float *Qp, *Kp, *Vp, *Sp, *AOp;
    cudaGetSymbolAddress((void**)&Qp,  g_Q);
    cudaGetSymbolAddress((void**)&Kp,  g_K);
    cudaGetSymbolAddress((void**)&Vp,  g_V);
    cudaGetSymbolAddress((void**)&Sp,  g_S);
    cudaGetSymbolAddress((void**)&AOp, g_AO);

    const float scale = 1.0f / 8.0f;   // 1/sqrt(64)

    // ---- input projections: X @ W^T (+bias) ----
    {
        dim3 grid(DD/128, (BB*LL)/128, 1);
        sgemm_kernel<128,128,8,8,8,true><<<grid, 256>>>(
            q, W_q, b_q, Qp, DD, DD, DD, DD, 1, 0,0,0,0,0,0, 1.f);
        sgemm_kernel<128,128,8,8,8,true><<<grid, 256>>>(
            k, W_k, nullptr, Kp, DD, DD, DD, DD, 1, 0,0,0,0,0,0, 1.f);
        sgemm_kernel<128,128,8,8,8,true><<<grid, 256>>>(
            v, W_v, nullptr, Vp, DD, DD, DD, DD, 1, 0,0,0,0,0,0, 1.f);
    }

    // ---- raw scores: S[b,h] = scale * Qh @ Kh^T  (K = 64) ----
    {
        dim3 grid(LL/128, LL/128, BB*HH);
        sgemm_kernel<128,128,8,8,8,true><<<grid, 256>>>(
            Qp, Kp, nullptr, Sp, DHH, DD, DD, LL,
            HH, LL*DD, DHH, LL*DD, DHH, HH*LL*LL, LL*LL, scale);
    }

    // ---- distmap bias + softmax -> attn (written directly into d_out) ----
    bias_softmax_kernel<<<BB*LL, 256>>>(
        Sp, dq, dkt, dkb, dks, relt, relb, W_w, W_b, outA);

    // ---- attn @ V  (B non-transposed, K = 1024, N = 64) ----
    {
        dim3 grid(DHH/64, LL/128, BB*HH);
        sgemm_kernel<128,64,16,8,4,false><<<grid, 256>>>(
            outA, Vp, nullptr, AOp, LL, LL, DD, DD,
            HH, HH*LL*LL, LL*LL, LL*DD, DHH, LL*DD, DHH, 1.f);
    }

    // ---- output projection: AO @ W_o^T + b_o -> out ----
    {
        dim3 grid(DD/128, (BB*LL)/128, 1);
        sgemm_kernel<128,128,8,8,8,true><<<grid, 256>>>(
            AOp, W_o, b_o, outO, DD, DD, DD, DD, 1, 0,0,0,0,0,0, 1.f);
    }
}

// round 3
// speedup vs baseline: 2.1289x; 2.1289x over previous
#include <cuda_runtime.h>
#include <cstdint>
#include <math.h>

#define BB  4
#define LL  1024
#define DD  1024
#define HH  16
#define DHH 64
#define FF  7

// ---- scratch (module-static device memory; no runtime allocation) ----
__device__ float g_Q[BB*LL*DD];
__device__ float g_K[BB*LL*DD];          // reused as Vt after scores GEMM
__device__ float g_V[BB*LL*DD];
__device__ float g_S[(size_t)BB*HH*LL*LL];   // raw scores
__device__ float g_AO[BB*LL*DD];             // attn @ V

// ============================================================================
// tf32 mma.sync helpers (arch-agnostic PTX; works on .target sm_103)
// ============================================================================
__device__ __forceinline__ uint32_t f2tf32(float f) {
    uint32_t r;
    asm volatile("cvt.rna.tf32.f32 %0, %1;" : "=r"(r) : "f"(f));
    return r;
}

#define MMA_TF32(c, a, b) \
    asm volatile("mma.sync.aligned.m16n8k8.row.col.f32.tf32.tf32.f32 " \
        "{%0,%1,%2,%3}, {%4,%5,%6,%7}, {%8,%9}, {%0,%1,%2,%3};" \
        : "+f"((c)[0]), "+f"((c)[1]), "+f"((c)[2]), "+f"((c)[3]) \
        : "r"((a)[0]), "r"((a)[1]), "r"((a)[2]), "r"((a)[3]), \
          "r"((b)[0]), "r"((b)[1]))

// ============================================================================
// Tensor-core tf32 GEMM: C[m,n] = alpha * sum_k A[m,k]*B[n,k] (+bias[n])
// BM=128, BK=32 fixed. BN/WM/WN templated. 256 threads = 8 warps.
// Smem layout: [row][k] with stride BK+4 (36 words) -> conflict-free frag LDS.
// Batched via blockIdx.z: offset(z) = (z/hmod)*S1 + (z%hmod)*S2 per tensor.
// ============================================================================
template<int BN, int WM, int WN>
__global__ __launch_bounds__(256)
void mma_gemm(const float* __restrict__ A, const float* __restrict__ B,
              const float* __restrict__ bias, float* __restrict__ C,
              int K, int lda, int ldb, int ldc, int hmod,
              long long aS1, long long aS2, long long bS1, long long bS2,
              long long cS1, long long cS2, float alpha)
{
    constexpr int BM = 128, BK = 32, LDS_ = BK + 4;
    constexpr int WGM = BM / WM;            // warps along m
    constexpr int MT = WM / 16, NT = WN / 8;
    constexpr int AV = BM * BK / 4 / 256;   // float4 loads per thread (A) = 4
    constexpr int BV = BN * BK / 4 / 256;   // (B) = 4 or 2
    static_assert(WGM * (BN / WN) == 8, "8 warps");

    extern __shared__ uint32_t sm[];
    uint32_t* As = sm;                      // [2][BM][LDS_]
    uint32_t* Bs = sm + 2 * BM * LDS_;      // [2][BN][LDS_]

    const int tid  = threadIdx.x;
    const int lane = tid & 31, wid = tid >> 5;
    const int wm = wid % WGM, wn = wid / WGM;
    const int z  = blockIdx.z;
    const int zd = z / hmod, zm = z % hmod;
    const float* Ab = A + zd * aS1 + zm * aS2;
    const float* Bb = B + zd * bS1 + zm * bS2;
    float*       Cb = C + zd * cS1 + zm * cS2;
    const int m0 = blockIdx.y * BM, n0 = blockIdx.x * BN;

    const int lrow = tid >> 3;              // 0..31
    const int kq   = tid & 7;               // k-quad
    const float* aG = Ab + (size_t)(m0 + lrow) * lda + kq * 4;
    const float* bG = Bb + (size_t)(n0 + lrow) * ldb + kq * 4;

    float acc[MT][NT][4];
    #pragma unroll
    for (int i = 0; i < MT; i++)
        #pragma unroll
        for (int j = 0; j < NT; j++)
            #pragma unroll
            for (int r = 0; r < 4; r++) acc[i][j][r] = 0.f;

    // ---- prologue: chunk 0 straight to smem buf 0 ----
    #pragma unroll
    for (int i = 0; i < AV; i++) {
        float4 v = *(const float4*)(aG + (size_t)i * 32 * lda);
        uint4 t = { f2tf32(v.x), f2tf32(v.y), f2tf32(v.z), f2tf32(v.w) };
        *(uint4*)(As + (lrow + i * 32) * LDS_ + kq * 4) = t;
    }
    #pragma unroll
    for (int i = 0; i < BV; i++) {
        float4 v = *(const float4*)(bG + (size_t)i * 32 * ldb);
        uint4 t = { f2tf32(v.x), f2tf32(v.y), f2tf32(v.z), f2tf32(v.w) };
        *(uint4*)(Bs + (lrow + i * 32) * LDS_ + kq * 4) = t;
    }
    __syncthreads();

    const int NC = K / BK;
    for (int c = 0; c < NC; c++) {
        float4 ra[AV], rb[BV];
        if (c + 1 < NC) {
            const float* ap = aG + (size_t)(c + 1) * BK;
            const float* bp = bG + (size_t)(c + 1) * BK;
            #pragma unroll
            for (int i = 0; i < AV; i++) ra[i] = *(const float4*)(ap + (size_t)i * 32 * lda);
            #pragma unroll
            for (int i = 0; i < BV; i++) rb[i] = *(const float4*)(bp + (size_t)i * 32 * ldb);
        }

        const uint32_t* Ac = As + (c & 1) * BM * LDS_;
        const uint32_t* Bc = Bs + (c & 1) * BN * LDS_;
        #pragma unroll
        for (int kk = 0; kk < BK; kk += 8) {
            uint32_t af[MT][4], bf[NT][2];
            #pragma unroll
            for (int mt = 0; mt < MT; mt++) {
                const uint32_t* p = Ac + (wm * WM + mt * 16 + (lane >> 2)) * LDS_ + kk + (lane & 3);
                af[mt][0] = p[0];
                af[mt][1] = p[8 * LDS_];
                af[mt][2] = p[4];
                af[mt][3] = p[8 * LDS_ + 4];
            }
            #pragma unroll
            for (int nt = 0; nt < NT; nt++) {
                const uint32_t* p = Bc + (wn * WN + nt * 8 + (lane >> 2)) * LDS_ + kk + (lane & 3);
                bf[nt][0] = p[0];
                bf[nt][1] = p[4];
            }
            #pragma unroll
            for (int mt = 0; mt < MT; mt++)
                #pragma unroll
                for (int nt = 0; nt < NT; nt++)
                    MMA_TF32(acc[mt][nt], af[mt], bf[nt]);
        }

        if (c + 1 < NC) {
            uint32_t* aD = As + ((c + 1) & 1) * BM * LDS_;
            uint32_t* bD = Bs + ((c + 1) & 1) * BN * LDS_;
            #pragma unroll
            for (int i = 0; i < AV; i++) {
                uint4 t = { f2tf32(ra[i].x), f2tf32(ra[i].y), f2tf32(ra[i].z), f2tf32(ra[i].w) };
                *(uint4*)(aD + (lrow + i * 32) * LDS_ + kq * 4) = t;
            }
            #pragma unroll
            for (int i = 0; i < BV; i++) {
                uint4 t = { f2tf32(rb[i].x), f2tf32(rb[i].y), f2tf32(rb[i].z), f2tf32(rb[i].w) };
                *(uint4*)(bD + (lrow + i * 32) * LDS_ + kq * 4) = t;
            }
            __syncthreads();
        }
    }

    // ---- epilogue ----
    #pragma unroll
    for (int mt = 0; mt < MT; mt++) {
        const int m = m0 + wm * WM + mt * 16 + (lane >> 2);
        #pragma unroll
        for (int nt = 0; nt < NT; nt++) {
            const int n = n0 + wn * WN + nt * 8 + 2 * (lane & 3);
            float bx = 0.f, by = 0.f;
            if (bias) { bx = bias[n]; by = bias[n + 1]; }
            float2 v0 = { acc[mt][nt][0] * alpha + bx, acc[mt][nt][1] * alpha + by };
            float2 v1 = { acc[mt][nt][2] * alpha + bx, acc[mt][nt][3] * alpha + by };
            *(float2*)(Cb + (size_t)m * ldc + n)       = v0;
            *(float2*)(Cb + (size_t)(m + 8) * ldc + n) = v1;
        }
    }
}

// ============================================================================
// per-head V transpose: Vt[(b*H+h)][n][k] = V[b][k][h*64+n]
// ============================================================================
__global__ __launch_bounds__(256)
void transposeV(const float* __restrict__ V, float* __restrict__ Vt)
{
    __shared__ float t[32][33];
    const int z = blockIdx.z;              // b*16+h
    const int b = z >> 4, h = z & 15;
    const int k0 = blockIdx.x * 32, n0 = blockIdx.y * 32;
    const int tx = threadIdx.x & 31, ty = threadIdx.x >> 5;
    #pragma unroll
    for (int i = 0; i < 4; i++)
        t[ty + 8 * i][tx] = V[((size_t)b * LL + k0 + ty + 8 * i) * DD + h * 64 + n0 + tx];
    __syncthreads();
    #pragma unroll
    for (int i = 0; i < 4; i++)
        Vt[((size_t)z * 64 + n0 + ty + 8 * i) * LL + k0 + tx] = t[tx][ty + 8 * i];
}

// ============================================================================
// Bias network + softmax
// ============================================================================
__device__ __forceinline__ float blockMax(float v, float* red) {
    #pragma unroll
    for (int o = 16; o; o >>= 1) v = fmaxf(v, __shfl_xor_sync(0xffffffffu, v, o));
    const int w = threadIdx.x >> 5, lane = threadIdx.x & 31;
    __syncthreads();
    if (lane == 0) red[w] = v;
    __syncthreads();
    float r = red[0];
    #pragma unroll
    for (int k = 1; k < 8; k++) r = fmaxf(r, red[k]);
    return r;
}
__device__ __forceinline__ float blockSum(float v, float* red) {
    #pragma unroll
    for (int o = 16; o; o >>= 1) v += __shfl_xor_sync(0xffffffffu, v, o);
    const int w = threadIdx.x >> 5, lane = threadIdx.x & 31;
    __syncthreads();
    if (lane == 0) red[w] = v;
    __syncthreads();
    float r = red[0];
    #pragma unroll
    for (int k = 1; k < 8; k++) r += red[k];
    return r;
}

__global__ __launch_bounds__(256)
void bias_softmax_kernel(const float* __restrict__ S,
                         const float* __restrict__ dq,
                         const float* __restrict__ dkt,
                         const float* __restrict__ dkb,
                         const float* __restrict__ dks,
                         const float* __restrict__ relt,
                         const float* __restrict__ relb,
                         const float* __restrict__ Ww,
                         const float* __restrict__ Wb,
                         float* __restrict__ attn)
{
    __shared__ float sDm[FF][LL];
    __shared__ float sW[2][HH*FF];
    __shared__ float red[8];

    const int bi  = blockIdx.x;
    const int b   = bi >> 10;
    const int tid = threadIdx.x;

    if (tid < HH*FF) { sW[0][tid] = Ww[tid]; sW[1][tid] = Wb[tid]; }

    const float dq0 = dq[bi*3+0], dq1 = dq[bi*3+1], dq2 = dq[bi*3+2];
    const size_t riBase = (size_t)bi * LL * 4;

    for (int j = tid; j < LL; j += 256) {
        const float* kt = dkt + ((size_t)b*LL + j)*3;
        const float* kb = dkb + ((size_t)b*LL + j)*3;
        const float* ks = dks + ((size_t)b*LL + j)*14;
        const float4 rt = *(const float4*)(relt + riBase + (size_t)j*4);
        const float4 rb = *(const float4*)(relb + riBase + (size_t)j*4);
        float top[FF] = { dq0-kt[0], dq1-kt[1], dq2-kt[2], rt.x, rt.y, rt.z, rt.w };
        float bot[FF] = { dq0-kb[0], dq1-kb[1], dq2-kb[2], rb.x, rb.y, rb.z, rb.w };
        #pragma unroll
        for (int f = 0; f < FF; f++)
            sDm[f][j] = fmaf(top[f], ks[f], bot[f]*ks[7+f]);
    }
    __syncthreads();

    const int i = bi & 1023;
    for (int h = 0; h < HH; h++) {
        const float* Srow = S + (((size_t)b*HH + h)*LL + i)*LL;
        float wW[FF], wB[FF];
        #pragma unroll
        for (int f = 0; f < FF; f++) { wW[f] = sW[0][h*FF+f]; wB[f] = sW[1][h*FF+f]; }

        float vals[4];
        float mx = -1e30f;
        #pragma unroll
        for (int r = 0; r < 4; r++) {
            const int j = tid + r*256;
            float dw = 0.f, db = 0.f;
            #pragma unroll
            for (int f = 0; f < FF; f++) {
                const float d = sDm[f][j];
                dw = fmaf(d, wW[f], dw);
                db = fmaf(d, wB[f], db);
            }
            const float sp = (dw > 15.f) ? dw : log1pf(__expf(dw));
            const float sc = fmaf(Srow[j], sp, db);
            vals[r] = sc;
            mx = fmaxf(mx, sc);
        }
        mx = blockMax(mx, red);

        float sum = 0.f;
        #pragma unroll
        for (int r = 0; r < 4; r++) {
            vals[r] = __expf(vals[r] - mx);
            sum += vals[r];
        }
        sum = blockSum(sum, red);
        const float inv = 1.f / sum;

        float* Arow = attn + (((size_t)b*HH + h)*LL + i)*LL;
        #pragma unroll
        for (int r = 0; r < 4; r++)
            Arow[tid + r*256] = vals[r] * inv;
    }
}

// ============================================================================
// launcher
// ============================================================================
extern "C" void kernel_launch(void* const* d_in, const int* in_sizes, int n_in,
                              void* d_out, int out_size)
{
    const float* q    = (const float*)d_in[0];
    const float* k    = (const float*)d_in[1];
    const float* v    = (const float*)d_in[2];
    const float* dq   = (const float*)d_in[3];
    const float* dkt  = (const float*)d_in[4];
    const float* dkb  = (const float*)d_in[5];
    const float* dks  = (const float*)d_in[6];
    const float* relt = (const float*)d_in[7];
    const float* relb = (const float*)d_in[8];
    const float* W_q  = (const float*)d_in[9];
    const float* b_q  = (const float*)d_in[10];
    const float* W_k  = (const float*)d_in[11];
    const float* W_v  = (const float*)d_in[12];
    // d_in[13] = W_c : unused by the outputs
    const float* W_w  = (const float*)d_in[14];
    const float* W_b  = (const float*)d_in[15];
    const float* W_o  = (const float*)d_in[16];
    const float* b_o  = (const float*)d_in[17];

    float* outO = (float*)d_out;               // [B,L,D]
    float* outA = outO + (size_t)BB*LL*DD;     // [B,H,L,L]

    float *Qp, *Kp, *Vp, *Sp, *AOp;
    cudaGetSymbolAddress((void**)&Qp,  g_Q);
    cudaGetSymbolAddress((void**)&Kp,  g_K);
    cudaGetSymbolAddress((void**)&Vp,  g_V);
    cudaGetSymbolAddress((void**)&Sp,  g_S);
    cudaGetSymbolAddress((void**)&AOp, g_AO);

    // dynamic smem: 2 buffers * (BM + BN) rows * 36 words * 4 bytes
    const int SM128 = 2 * (128 + 128) * 36 * 4;   // 73728
    const int SM64  = 2 * (128 + 64)  * 36 * 4;   // 55296
    cudaFuncSetAttribute(mma_gemm<128,64,32>, cudaFuncAttributeMaxDynamicSharedMemorySize, SM128);
    cudaFuncSetAttribute(mma_gemm<64,32,32>,  cudaFuncAttributeMaxDynamicSharedMemorySize, SM64);

    // ---- projections: X @ W^T (+bias), M=4096, N=1024, K=1024 ----
    {
        dim3 grid(DD/128, (BB*LL)/128, 1);
        mma_gemm<128,64,32><<<grid, 256, SM128>>>(q, W_q, b_q, Qp, DD, DD, DD, DD,
                                                  1, 0,0,0,0,0,0, 1.f);
        mma_gemm<128,64,32><<<grid, 256, SM128>>>(k, W_k, nullptr, Kp, DD, DD, DD, DD,
                                                  1, 0,0,0,0,0,0, 1.f);
        mma_gemm<128,64,32><<<grid, 256, SM128>>>(v, W_v, nullptr, Vp, DD, DD, DD, DD,
                                                  1, 0,0,0,0,0,0, 1.f);
    }

    // ---- scores: S[b,h] = (1/8) Qh @ Kh^T, M=N=1024, K=64, batch 64 ----
    {
        dim3 grid(LL/128, LL/128, BB*HH);
        mma_gemm<128,64,32><<<grid, 256, SM128>>>(Qp, Kp, nullptr, Sp, DHH, DD, DD, LL,
            HH, (long long)LL*DD, 64, (long long)LL*DD, 64,
            (long long)HH*LL*LL, (long long)LL*LL, 0.125f);
    }

    // ---- V per-head transpose into g_K (free after scores): Vt[z][n][k] ----
    {
        dim3 grid(LL/32, DHH/32, BB*HH);
        transposeV<<<grid, 256>>>(Vp, Kp);
    }

    // ---- distmap bias + softmax -> attn (direct to d_out) ----
    bias_softmax_kernel<<<BB*LL, 256>>>(
        Sp, dq, dkt, dkb, dks, relt, relb, W_w, W_b, outA);

    // ---- attn @ Vh : M=1024, N=64, K=1024, batch 64 ----
    {
        dim3 grid(1, LL/128, BB*HH);
        mma_gemm<64,32,32><<<grid, 256, SM64>>>(outA, Kp, nullptr, AOp, LL, LL, LL, DD,
            HH, (long long)HH*LL*LL, (long long)LL*LL,
            (long long)HH*DHH*LL, (long long)DHH*LL,
            (long long)LL*DD, 64, 1.f);
    }

    // ---- output projection: AO @ W_o^T + b_o ----
    {
        dim3 grid(DD/128, (BB*LL)/128, 1);
        mma_gemm<128,64,32><<<grid, 256, SM128>>>(AOp, W_o, b_o, outO, DD, DD, DD, DD,
                                                  1, 0,0,0,0,0,0, 1.f);
    }
}

// round 4
// speedup vs baseline: 2.3329x; 1.0958x over previous
#include <cuda_runtime.h>
#include <cstdint>
#include <math.h>

#define BB  4
#define LL  1024
#define DD  1024
#define HH  16
#define DHH 64
#define FF  7

// ---- scratch (module-static device memory; no runtime allocation) ----
__device__ __align__(16) float g_Q[BB*LL*DD];
__device__ __align__(16) float g_K[BB*LL*DD];          // reused as Vt
__device__ __align__(16) float g_V[BB*LL*DD];
__device__ __align__(16) float g_S[(size_t)BB*HH*LL*LL];
__device__ __align__(16) float g_AO[BB*LL*DD];

// ============================================================================
// helpers
// ============================================================================
__device__ __forceinline__ uint32_t smem_u32(const void* p) {
    uint32_t a;
    asm("{ .reg .u64 t; cvta.to.shared.u64 t, %1; cvt.u32.u64 %0, t; }" : "=r"(a) : "l"(p));
    return a;
}
__device__ __forceinline__ uint32_t f2tf32(float f) {
    uint32_t r;
    asm volatile("cvt.rna.tf32.f32 %0, %1;" : "=r"(r) : "f"(f));
    return r;
}
__device__ __forceinline__ void cp16(uint32_t s, const void* g) {
    asm volatile("cp.async.cg.shared.global [%0], [%1], 16;" :: "r"(s), "l"(g) : "memory");
}
#define CP_COMMIT() asm volatile("cp.async.commit_group;" ::: "memory")
#define CP_WAIT1()  asm volatile("cp.async.wait_group 1;" ::: "memory")

#define MMA_TF32(c, a, b) \
    asm volatile("mma.sync.aligned.m16n8k8.row.col.f32.tf32.tf32.f32 " \
        "{%0,%1,%2,%3}, {%4,%5,%6,%7}, {%8,%9}, {%0,%1,%2,%3};" \
        : "+f"((c)[0]), "+f"((c)[1]), "+f"((c)[2]), "+f"((c)[3]) \
        : "r"((a)[0]), "r"((a)[1]), "r"((a)[2]), "r"((a)[3]), \
          "r"((b)[0]), "r"((b)[1]))

// ============================================================================
// Tensor-core tf32 GEMM: C[m,n] = alpha * sum_k A[m,k]*B[n,k] (+bias[n])
// 64x64 warp tiles; BM x BN block; BK=32; 3-stage cp.async pipeline.
// Batched via blockIdx.z: offset(z) = (z/hmod)*S1 + (z%hmod)*S2 per tensor.
// ============================================================================
template<int BM, int BN>
__global__ void __launch_bounds__((BM/64)*(BN/64)*32)
mma_gemm(const float* __restrict__ A, const float* __restrict__ B,
         const float* __restrict__ bias, float* __restrict__ C,
         int K, int lda, int ldb, int ldc, int hmod,
         long long aS1, long long aS2, long long bS1, long long bS2,
         long long cS1, long long cS2, float alpha)
{
    constexpr int WARPS_M = BM / 64, WARPS_N = BN / 64;
    constexpr int NTHR = WARPS_M * WARPS_N * 32;
    constexpr int BK = 32, LDSW = 36;
    constexpr int STW = (BM + BN) * LDSW;        // words per stage
    constexpr int A_IT = BM * 8 / NTHR;          // cp.async per thread (A)
    constexpr int B_IT = BN * 8 / NTHR;
    constexpr int RSTEP = NTHR / 8;              // row step per iteration
    constexpr int MT = 4, NT = 8;

    extern __shared__ float sm[];

    const int tid = threadIdx.x, lane = tid & 31, wid = tid >> 5;
    const int wm = wid % WARPS_M, wn = wid / WARPS_M;
    const int z = blockIdx.z, zd = z / hmod, zm = z % hmod;
    const float* Ab = A + zd * aS1 + zm * aS2;
    const float* Bb = B + zd * bS1 + zm * bS2;
    float*       Cb = C + zd * cS1 + zm * cS2;
    const int m0 = blockIdx.y * BM, n0 = blockIdx.x * BN;

    // ---- loader bases: thread handles rows (tid>>3)+it*RSTEP, quad tid&7 ----
    const int lrow = tid >> 3, lq = tid & 7;
    const float* aG = Ab + (size_t)(m0 + lrow) * lda + lq * 4;
    const float* bG = Bb + (size_t)(n0 + lrow) * ldb + lq * 4;
    const uint32_t smB = smem_u32(sm);
    const uint32_t aSo = (uint32_t)(lrow * LDSW + lq * 4) * 4;
    const uint32_t bSo = (uint32_t)((BM + lrow) * LDSW + lq * 4) * 4;

    float acc[MT][NT][4];
    #pragma unroll
    for (int i = 0; i < MT; i++)
        #pragma unroll
        for (int j = 0; j < NT; j++)
            #pragma unroll
            for (int r = 0; r < 4; r++) acc[i][j][r] = 0.f;

    const int NC = K / BK;

    auto LOAD = [&](int c, int s) {
        const uint32_t stb = smB + (uint32_t)s * STW * 4;
        const float* ap = aG + c * BK;
        const float* bp = bG + c * BK;
        #pragma unroll
        for (int it = 0; it < A_IT; it++)
            cp16(stb + aSo + (uint32_t)it * RSTEP * LDSW * 4,
                 ap + (size_t)it * RSTEP * lda);
        #pragma unroll
        for (int it = 0; it < B_IT; it++)
            cp16(stb + bSo + (uint32_t)it * RSTEP * LDSW * 4,
                 bp + (size_t)it * RSTEP * ldb);
    };

    LOAD(0, 0); CP_COMMIT();
    if (NC > 1) LOAD(1, 1);
    CP_COMMIT();

    const int aFr = (wm * 64 + (lane >> 2)) * LDSW + (lane & 3);
    const int bFr = (BM + wn * 64 + (lane >> 2)) * LDSW + (lane & 3);

    for (int c = 0; c < NC; c++) {
        CP_WAIT1();
        __syncthreads();
        if (c + 2 < NC) LOAD(c + 2, (c + 2) % 3);
        CP_COMMIT();

        const float* sA = sm + (c % 3) * STW + aFr;
        const float* sB = sm + (c % 3) * STW + bFr;
        #pragma unroll
        for (int kk = 0; kk < 4; kk++) {
            uint32_t af[MT][4], bf[NT][2];
            #pragma unroll
            for (int mt = 0; mt < MT; mt++) {
                af[mt][0] = f2tf32(sA[mt * 16 * LDSW + kk * 8]);
                af[mt][1] = f2tf32(sA[(mt * 16 + 8) * LDSW + kk * 8]);
                af[mt][2] = f2tf32(sA[mt * 16 * LDSW + kk * 8 + 4]);
                af[mt][3] = f2tf32(sA[(mt * 16 + 8) * LDSW + kk * 8 + 4]);
            }
            #pragma unroll
            for (int nt = 0; nt < NT; nt++) {
                bf[nt][0] = f2tf32(sB[nt * 8 * LDSW + kk * 8]);
                bf[nt][1] = f2tf32(sB[nt * 8 * LDSW + kk * 8 + 4]);
            }
            #pragma unroll
            for (int mt = 0; mt < MT; mt++)
                #pragma unroll
                for (int nt = 0; nt < NT; nt++)
                    MMA_TF32(acc[mt][nt], af[mt], bf[nt]);
        }
    }

    // ---- epilogue ----
    #pragma unroll
    for (int mt = 0; mt < MT; mt++) {
        const int m = m0 + wm * 64 + mt * 16 + (lane >> 2);
        #pragma unroll
        for (int nt = 0; nt < NT; nt++) {
            const int n = n0 + wn * 64 + nt * 8 + 2 * (lane & 3);
            float bx = 0.f, by = 0.f;
            if (bias) { bx = bias[n]; by = bias[n + 1]; }
            float2 v0 = { acc[mt][nt][0] * alpha + bx, acc[mt][nt][1] * alpha + by };
            float2 v1 = { acc[mt][nt][2] * alpha + bx, acc[mt][nt][3] * alpha + by };
            *(float2*)(Cb + (size_t)m * ldc + n)       = v0;
            *(float2*)(Cb + (size_t)(m + 8) * ldc + n) = v1;
        }
    }
}

// ============================================================================
// per-head V transpose: Vt[(b*H+h)][n][k] = V[b][k][h*64+n]
// ============================================================================
__global__ __launch_bounds__(256)
void transposeV(const float* __restrict__ V, float* __restrict__ Vt)
{
    __shared__ float t[32][33];
    const int z = blockIdx.z;              // b*16+h
    const int b = z >> 4, h = z & 15;
    const int k0 = blockIdx.x * 32, n0 = blockIdx.y * 32;
    const int tx = threadIdx.x & 31, ty = threadIdx.x >> 5;
    #pragma unroll
    for (int i = 0; i < 4; i++)
        t[ty + 8 * i][tx] = V[((size_t)b * LL + k0 + ty + 8 * i) * DD + h * 64 + n0 + tx];
    __syncthreads();
    #pragma unroll
    for (int i = 0; i < 4; i++)
        Vt[((size_t)z * 64 + n0 + ty + 8 * i) * LL + k0 + tx] = t[tx][ty + 8 * i];
}

// ============================================================================
// Bias network + softmax
// ============================================================================
__device__ __forceinline__ float blockMax(float v, float* red) {
    #pragma unroll
    for (int o = 16; o; o >>= 1) v = fmaxf(v, __shfl_xor_sync(0xffffffffu, v, o));
    const int w = threadIdx.x >> 5, lane = threadIdx.x & 31;
    __syncthreads();
    if (lane == 0) red[w] = v;
    __syncthreads();
    float r = red[0];
    #pragma unroll
    for (int k = 1; k < 8; k++) r = fmaxf(r, red[k]);
    return r;
}
__device__ __forceinline__ float blockSum(float v, float* red) {
    #pragma unroll
    for (int o = 16; o; o >>= 1) v += __shfl_xor_sync(0xffffffffu, v, o);
    const int w = threadIdx.x >> 5, lane = threadIdx.x & 31;
    __syncthreads();
    if (lane == 0) red[w] = v;
    __syncthreads();
    float r = red[0];
    #pragma unroll
    for (int k = 1; k < 8; k++) r += red[k];
    return r;
}

__global__ __launch_bounds__(256)
void bias_softmax_kernel(const float* __restrict__ S,
                         const float* __restrict__ dq,
                         const float* __restrict__ dkt,
                         const float* __restrict__ dkb,
                         const float* __restrict__ dks,
                         const float* __restrict__ relt,
                         const float* __restrict__ relb,
                         const float* __restrict__ Ww,
                         const float* __restrict__ Wb,
                         float* __restrict__ attn)
{
    __shared__ float sDm[FF][LL];
    __shared__ float sW[2][HH*FF];
    __shared__ float red[8];

    const int bi  = blockIdx.x;
    const int b   = bi >> 10;
    const int tid = threadIdx.x;

    if (tid < HH*FF) { sW[0][tid] = Ww[tid]; sW[1][tid] = Wb[tid]; }

    const float dq0 = dq[bi*3+0], dq1 = dq[bi*3+1], dq2 = dq[bi*3+2];
    const size_t riBase = (size_t)bi * LL * 4;

    for (int j = tid; j < LL; j += 256) {
        const float* kt = dkt + ((size_t)b*LL + j)*3;
        const float* kb = dkb + ((size_t)b*LL + j)*3;
        const float* ks = dks + ((size_t)b*LL + j)*14;
        const float4 rt = *(const float4*)(relt + riBase + (size_t)j*4);
        const float4 rb = *(const float4*)(relb + riBase + (size_t)j*4);
        float top[FF] = { dq0-kt[0], dq1-kt[1], dq2-kt[2], rt.x, rt.y, rt.z, rt.w };
        float bot[FF] = { dq0-kb[0], dq1-kb[1], dq2-kb[2], rb.x, rb.y, rb.z, rb.w };
        #pragma unroll
        for (int f = 0; f < FF; f++)
            sDm[f][j] = fmaf(top[f], ks[f], bot[f]*ks[7+f]);
    }
    __syncthreads();

    const int i = bi & 1023;
    for (int h = 0; h < HH; h++) {
        const float* Srow = S + (((size_t)b*HH + h)*LL + i)*LL;
        float wW[FF], wB[FF];
        #pragma unroll
        for (int f = 0; f < FF; f++) { wW[f] = sW[0][h*FF+f]; wB[f] = sW[1][h*FF+f]; }

        float vals[4];
        float mx = -1e30f;
        #pragma unroll
        for (int r = 0; r < 4; r++) {
            const int j = tid + r*256;
            float dw = 0.f, db = 0.f;
            #pragma unroll
            for (int f = 0; f < FF; f++) {
                const float d = sDm[f][j];
                dw = fmaf(d, wW[f], dw);
                db = fmaf(d, wB[f], db);
            }
            const float sp = (dw > 15.f) ? dw : log1pf(__expf(dw));
            const float sc = fmaf(Srow[j], sp, db);
            vals[r] = sc;
            mx = fmaxf(mx, sc);
        }
        mx = blockMax(mx, red);

        float sum = 0.f;
        #pragma unroll
        for (int r = 0; r < 4; r++) {
            vals[r] = __expf(vals[r] - mx);
            sum += vals[r];
        }
        sum = blockSum(sum, red);
        const float inv = 1.f / sum;

        float* Arow = attn + (((size_t)b*HH + h)*LL + i)*LL;
        #pragma unroll
        for (int r = 0; r < 4; r++)
            Arow[tid + r*256] = vals[r] * inv;
    }
}

// ============================================================================
// launcher
// ============================================================================
extern "C" void kernel_launch(void* const* d_in, const int* in_sizes, int n_in,
                              void* d_out, int out_size)
{
    const float* q    = (const float*)d_in[0];
    const float* k    = (const float*)d_in[1];
    const float* v    = (const float*)d_in[2];
    const float* dq   = (const float*)d_in[3];
    const float* dkt  = (const float*)d_in[4];
    const float* dkb  = (const float*)d_in[5];
    const float* dks  = (const float*)d_in[6];
    const float* relt = (const float*)d_in[7];
    const float* relb = (const float*)d_in[8];
    const float* W_q  = (const float*)d_in[9];
    const float* b_q  = (const float*)d_in[10];
    const float* W_k  = (const float*)d_in[11];
    const float* W_v  = (const float*)d_in[12];
    // d_in[13] = W_c : unused by the outputs
    const float* W_w  = (const float*)d_in[14];
    const float* W_b  = (const float*)d_in[15];
    const float* W_o  = (const float*)d_in[16];
    const float* b_o  = (const float*)d_in[17];

    float* outO = (float*)d_out;               // [B,L,D]
    float* outA = outO + (size_t)BB*LL*DD;     // [B,H,L,L]

    float *Qp, *Kp, *Vp, *Sp, *AOp;
    cudaGetSymbolAddress((void**)&Qp,  g_Q);
    cudaGetSymbolAddress((void**)&Kp,  g_K);
    cudaGetSymbolAddress((void**)&Vp,  g_V);
    cudaGetSymbolAddress((void**)&Sp,  g_S);
    cudaGetSymbolAddress((void**)&AOp, g_AO);

    // dynamic smem: 3 stages * (BM+BN) rows * 36 words * 4 bytes
    const int SM_BIG = 3 * (128 + 256) * 36 * 4;   // 165888
    const int SM_AV  = 3 * (256 + 64)  * 36 * 4;   // 138240
    cudaFuncSetAttribute(mma_gemm<128,256>, cudaFuncAttributeMaxDynamicSharedMemorySize, SM_BIG);
    cudaFuncSetAttribute(mma_gemm<256,64>,  cudaFuncAttributeMaxDynamicSharedMemorySize, SM_AV);

    // ---- projections: X @ W^T (+bias), M=4096, N=1024, K=1024 ----
    {
        dim3 grid(DD/256, (BB*LL)/128, 1);
        mma_gemm<128,256><<<grid, 256, SM_BIG>>>(q, W_q, b_q, Qp, DD, DD, DD, DD,
                                                 1, 0,0,0,0,0,0, 1.f);
        mma_gemm<128,256><<<grid, 256, SM_BIG>>>(k, W_k, nullptr, Kp, DD, DD, DD, DD,
                                                 1, 0,0,0,0,0,0, 1.f);
        mma_gemm<128,256><<<grid, 256, SM_BIG>>>(v, W_v, nullptr, Vp, DD, DD, DD, DD,
                                                 1, 0,0,0,0,0,0, 1.f);
    }

    // ---- scores: S[b,h] = (1/8) Qh @ Kh^T, M=N=1024, K=64, batch 64 ----
    {
        dim3 grid(LL/256, LL/128, BB*HH);
        mma_gemm<128,256><<<grid, 256, SM_BIG>>>(Qp, Kp, nullptr, Sp, DHH, DD, DD, LL,
            HH, (long long)LL*DD, 64, (long long)LL*DD, 64,
            (long long)HH*LL*LL, (long long)LL*LL, 0.125f);
    }

    // ---- V per-head transpose into g_K (free after scores): Vt[z][n][k] ----
    {
        dim3 grid(LL/32, DHH/32, BB*HH);
        transposeV<<<grid, 256>>>(Vp, Kp);
    }

    // ---- distmap bias + softmax -> attn (direct to d_out) ----
    bias_softmax_kernel<<<BB*LL, 256>>>(
        Sp, dq, dkt, dkb, dks, relt, relb, W_w, W_b, outA);

    // ---- attn @ Vh : M=1024, N=64, K=1024, batch 64 ----
    {
        dim3 grid(1, LL/256, BB*HH);
        mma_gemm<256,64><<<grid, 128, SM_AV>>>(outA, Kp, nullptr, AOp, LL, LL, LL, DD,
            HH, (long long)HH*LL*LL, (long long)LL*LL,
            (long long)HH*DHH*LL, (long long)DHH*LL,
            (long long)LL*DD, 64, 1.f);
    }

    // ---- output projection: AO @ W_o^T + b_o ----
    {
        dim3 grid(DD/256, (BB*LL)/128, 1);
        mma_gemm<128,256><<<grid, 256, SM_BIG>>>(AOp, W_o, b_o, outO, DD, DD, DD, DD,
                                                 1, 0,0,0,0,0,0, 1.f);
    }
}

// round 5
// speedup vs baseline: 2.3648x; 1.0137x over previous
#include <cuda_runtime.h>
#include <cstdint>
#include <math.h>

#define BB  4
#define LL  1024
#define DD  1024
#define HH  16
#define DHH 64
#define FF  7

// ---- scratch (module-static device memory; no runtime allocation) ----
__device__ __align__(16) float g_Q[BB*LL*DD];
__device__ __align__(16) float g_K[BB*LL*DD];          // reused as Vt
__device__ __align__(16) float g_V[BB*LL*DD];
__device__ __align__(16) float g_S[(size_t)BB*HH*LL*LL];
__device__ __align__(16) float g_AO[BB*LL*DD];
// pre-rounded (tf32) copies of raw MMA operands
__device__ __align__(16) float g_qr[BB*LL*DD];
__device__ __align__(16) float g_kr[BB*LL*DD];
__device__ __align__(16) float g_vr[BB*LL*DD];
__device__ __align__(16) float g_Wqr[DD*DD];
__device__ __align__(16) float g_Wkr[DD*DD];
__device__ __align__(16) float g_Wvr[DD*DD];
__device__ __align__(16) float g_Wor[DD*DD];

// ============================================================================
// helpers
// ============================================================================
__device__ __forceinline__ uint32_t smem_u32(const void* p) {
    uint32_t a;
    asm("{ .reg .u64 t; cvta.to.shared.u64 t, %1; cvt.u32.u64 %0, t; }" : "=r"(a) : "l"(p));
    return a;
}
__device__ __forceinline__ uint32_t f2tf32(float f) {
    uint32_t r;
    asm volatile("cvt.rna.tf32.f32 %0, %1;" : "=r"(r) : "f"(f));
    return r;
}
__device__ __forceinline__ float roundtf(float f) {
    return __uint_as_float(f2tf32(f));
}
__device__ __forceinline__ void cp16(uint32_t s, const void* g) {
    asm volatile("cp.async.cg.shared.global [%0], [%1], 16;" :: "r"(s), "l"(g) : "memory");
}
#define CP_COMMIT() asm volatile("cp.async.commit_group;" ::: "memory")
#define CP_WAIT1()  asm volatile("cp.async.wait_group 1;" ::: "memory")

#define LDSM4(r0, r1, r2, r3, addr) \
    asm volatile("ldmatrix.sync.aligned.m8n8.x4.shared.b16 {%0,%1,%2,%3}, [%4];" \
        : "=r"(r0), "=r"(r1), "=r"(r2), "=r"(r3) : "r"(addr))

#define MMA_TF32(c, a, b) \
    asm volatile("mma.sync.aligned.m16n8k8.row.col.f32.tf32.tf32.f32 " \
        "{%0,%1,%2,%3}, {%4,%5,%6,%7}, {%8,%9}, {%0,%1,%2,%3};" \
        : "+f"((c)[0]), "+f"((c)[1]), "+f"((c)[2]), "+f"((c)[3]) \
        : "r"((a)[0]), "r"((a)[1]), "r"((a)[2]), "r"((a)[3]), \
          "r"((b)[0]), "r"((b)[1]))

// ============================================================================
// elementwise tf32 rounding pass (float4-vectorized, grid-stride)
// ============================================================================
__global__ __launch_bounds__(256)
void round_tf32(const float4* __restrict__ in, float4* __restrict__ out, int n4)
{
    for (int i = blockIdx.x * 256 + threadIdx.x; i < n4; i += gridDim.x * 256) {
        float4 v = in[i];
        v.x = roundtf(v.x); v.y = roundtf(v.y);
        v.z = roundtf(v.z); v.w = roundtf(v.w);
        out[i] = v;
    }
}

// ============================================================================
// Tensor-core tf32 GEMM: C[m,n] = alpha * sum_k A[m,k]*B[n,k] (+bias[n])
// 64x64 warp tiles; BM x BN block; BK=32; 3-stage cp.async; ldmatrix frags.
// All A/B inputs must be pre-rounded to tf32. RC: round C output to tf32.
// ============================================================================
template<int BM, int BN, bool RC>
__global__ void __launch_bounds__((BM/64)*(BN/64)*32)
mma_gemm(const float* __restrict__ A, const float* __restrict__ B,
         const float* __restrict__ bias, float* __restrict__ C,
         int K, int lda, int ldb, int ldc, int hmod,
         long long aS1, long long aS2, long long bS1, long long bS2,
         long long cS1, long long cS2, float alpha)
{
    constexpr int WARPS_M = BM / 64, WARPS_N = BN / 64;
    constexpr int NTHR = WARPS_M * WARPS_N * 32;
    constexpr int BK = 32, LDSW = 36;
    constexpr int STW = (BM + BN) * LDSW;        // words per stage
    constexpr int A_IT = BM * 8 / NTHR;
    constexpr int B_IT = BN * 8 / NTHR;
    constexpr int RSTEP = NTHR / 8;
    constexpr int MT = 4, NT = 8;

    extern __shared__ float sm[];

    const int tid = threadIdx.x, lane = tid & 31, wid = tid >> 5;
    const int wm = wid % WARPS_M, wn = wid / WARPS_M;
    const int z = blockIdx.z, zd = z / hmod, zm = z % hmod;
    const float* Ab = A + zd * aS1 + zm * aS2;
    const float* Bb = B + zd * bS1 + zm * bS2;
    float*       Cb = C + zd * cS1 + zm * cS2;
    const int m0 = blockIdx.y * BM, n0 = blockIdx.x * BN;

    // ---- cp.async loader ----
    const int lrow = tid >> 3, lq = tid & 7;
    const float* aG = Ab + (size_t)(m0 + lrow) * lda + lq * 4;
    const float* bG = Bb + (size_t)(n0 + lrow) * ldb + lq * 4;
    const uint32_t smB = smem_u32(sm);
    const uint32_t aSo = (uint32_t)(lrow * LDSW + lq * 4) * 4;
    const uint32_t bSo = (uint32_t)((BM + lrow) * LDSW + lq * 4) * 4;

    // ---- ldmatrix per-thread addressing ----
    // A x4: matrix j = lane>>3 -> {row half = j&1, k half = j>>1}, row lane&7
    const int mj = lane >> 3, mr = lane & 7;
    const int rowA  = wm * 64 + ((mj & 1) << 3) + mr;
    const int kOffA = (mj >> 1) << 2;
    // B x4 (pair p): matrix j -> {nt = 2p + (j>>1), k half = j&1}
    const int rowB  = BM + wn * 64 + ((mj >> 1) << 3) + mr;
    const int kOffB = (mj & 1) << 2;

    float acc[MT][NT][4];
    #pragma unroll
    for (int i = 0; i < MT; i++)
        #pragma unroll
        for (int j = 0; j < NT; j++)
            #pragma unroll
            for (int r = 0; r < 4; r++) acc[i][j][r] = 0.f;

    const int NC = K / BK;

    auto LOAD = [&](int c, int s) {
        const uint32_t stb = smB + (uint32_t)s * STW * 4;
        const float* ap = aG + c * BK;
        const float* bp = bG + c * BK;
        #pragma unroll
        for (int it = 0; it < A_IT; it++)
            cp16(stb + aSo + (uint32_t)it * RSTEP * LDSW * 4,
                 ap + (size_t)it * RSTEP * lda);
        #pragma unroll
        for (int it = 0; it < B_IT; it++)
            cp16(stb + bSo + (uint32_t)it * RSTEP * LDSW * 4,
                 bp + (size_t)it * RSTEP * ldb);
    };

    LOAD(0, 0); CP_COMMIT();
    if (NC > 1) LOAD(1, 1);
    CP_COMMIT();

    for (int c = 0; c < NC; c++) {
        CP_WAIT1();
        __syncthreads();
        if (c + 2 < NC) LOAD(c + 2, (c + 2) % 3);
        CP_COMMIT();

        const uint32_t stb = smB + (uint32_t)(c % 3) * STW * 4;
        #pragma unroll
        for (int kk = 0; kk < 4; kk++) {
            uint32_t af[MT][4], bf[NT][2];
            #pragma unroll
            for (int mt = 0; mt < MT; mt++) {
                const uint32_t ad = stb +
                    (uint32_t)((rowA + mt * 16) * LDSW + kk * 8 + kOffA) * 4;
                LDSM4(af[mt][0], af[mt][1], af[mt][2], af[mt][3], ad);
            }
            #pragma unroll
            for (int p = 0; p < 4; p++) {
                const uint32_t bd = stb +
                    (uint32_t)((rowB + p * 16) * LDSW + kk * 8 + kOffB) * 4;
                LDSM4(bf[2*p][0], bf[2*p][1], bf[2*p+1][0], bf[2*p+1][1], bd);
            }
            #pragma unroll
            for (int mt = 0; mt < MT; mt++)
                #pragma unroll
                for (int nt = 0; nt < NT; nt++)
                    MMA_TF32(acc[mt][nt], af[mt], bf[nt]);
        }
    }

    // ---- epilogue ----
    #pragma unroll
    for (int mt = 0; mt < MT; mt++) {
        const int m = m0 + wm * 64 + mt * 16 + (lane >> 2);
        #pragma unroll
        for (int nt = 0; nt < NT; nt++) {
            const int n = n0 + wn * 64 + nt * 8 + 2 * (lane & 3);
            float bx = 0.f, by = 0.f;
            if (bias) { bx = bias[n]; by = bias[n + 1]; }
            float2 v0 = { acc[mt][nt][0] * alpha + bx, acc[mt][nt][1] * alpha + by };
            float2 v1 = { acc[mt][nt][2] * alpha + bx, acc[mt][nt][3] * alpha + by };
            if (RC) {
                v0.x = roundtf(v0.x); v0.y = roundtf(v0.y);
                v1.x = roundtf(v1.x); v1.y = roundtf(v1.y);
            }
            *(float2*)(Cb + (size_t)m * ldc + n)       = v0;
            *(float2*)(Cb + (size_t)(m + 8) * ldc + n) = v1;
        }
    }
}

// ============================================================================
// per-head V transpose: Vt[(b*H+h)][n][k] = V[b][k][h*64+n]
// ============================================================================
__global__ __launch_bounds__(256)
void transposeV(const float* __restrict__ V, float* __restrict__ Vt)
{
    __shared__ float t[32][33];
    const int z = blockIdx.z;              // b*16+h
    const int b = z >> 4, h = z & 15;
    const int k0 = blockIdx.x * 32, n0 = blockIdx.y * 32;
    const int tx = threadIdx.x & 31, ty = threadIdx.x >> 5;
    #pragma unroll
    for (int i = 0; i < 4; i++)
        t[ty + 8 * i][tx] = V[((size_t)b * LL + k0 + ty + 8 * i) * DD + h * 64 + n0 + tx];
    __syncthreads();
    #pragma unroll
    for (int i = 0; i < 4; i++)
        Vt[((size_t)z * 64 + n0 + ty + 8 * i) * LL + k0 + tx] = t[tx][ty + 8 * i];
}

// ============================================================================
// Bias network + softmax (attn rounded to tf32 at store -> MMA-ready)
// ============================================================================
__device__ __forceinline__ float blockMax(float v, float* red) {
    #pragma unroll
    for (int o = 16; o; o >>= 1) v = fmaxf(v, __shfl_xor_sync(0xffffffffu, v, o));
    const int w = threadIdx.x >> 5, lane = threadIdx.x & 31;
    __syncthreads();
    if (lane == 0) red[w] = v;
    __syncthreads();
    float r = red[0];
    #pragma unroll
    for (int k = 1; k < 8; k++) r = fmaxf(r, red[k]);
    return r;
}
__device__ __forceinline__ float blockSum(float v, float* red) {
    #pragma unroll
    for (int o = 16; o; o >>= 1) v += __shfl_xor_sync(0xffffffffu, v, o);
    const int w = threadIdx.x >> 5, lane = threadIdx.x & 31;
    __syncthreads();
    if (lane == 0) red[w] = v;
    __syncthreads();
    float r = red[0];
    #pragma unroll
    for (int k = 1; k < 8; k++) r += red[k];
    return r;
}

__global__ __launch_bounds__(256)
void bias_softmax_kernel(const float* __restrict__ S,
                         const float* __restrict__ dq,
                         const float* __restrict__ dkt,
                         const float* __restrict__ dkb,
                         const float* __restrict__ dks,
                         const float* __restrict__ relt,
                         const float* __restrict__ relb,
                         const float* __restrict__ Ww,
                         const float* __restrict__ Wb,
                         float* __restrict__ attn)
{
    __shared__ float sDm[FF][LL];
    __shared__ float sW[2][HH*FF];
    __shared__ float red[8];

    const int bi  = blockIdx.x;
    const int b   = bi >> 10;
    const int tid = threadIdx.x;

    if (tid < HH*FF) { sW[0][tid] = Ww[tid]; sW[1][tid] = Wb[tid]; }

    const float dq0 = dq[bi*3+0], dq1 = dq[bi*3+1], dq2 = dq[bi*3+2];
    const size_t riBase = (size_t)bi * LL * 4;

    for (int j = tid; j < LL; j += 256) {
        const float* kt = dkt + ((size_t)b*LL + j)*3;
        const float* kb = dkb + ((size_t)b*LL + j)*3;
        const float* ks = dks + ((size_t)b*LL + j)*14;
        const float4 rt = *(const float4*)(relt + riBase + (size_t)j*4);
        const float4 rb = *(const float4*)(relb + riBase + (size_t)j*4);
        float top[FF] = { dq0-kt[0], dq1-kt[1], dq2-kt[2], rt.x, rt.y, rt.z, rt.w };
        float bot[FF] = { dq0-kb[0], dq1-kb[1], dq2-kb[2], rb.x, rb.y, rb.z, rb.w };
        #pragma unroll
        for (int f = 0; f < FF; f++)
            sDm[f][j] = fmaf(top[f], ks[f], bot[f]*ks[7+f]);
    }
    __syncthreads();

    const int i = bi & 1023;
    for (int h = 0; h < HH; h++) {
        const float* Srow = S + (((size_t)b*HH + h)*LL + i)*LL;
        float wW[FF], wB[FF];
        #pragma unroll
        for (int f = 0; f < FF; f++) { wW[f] = sW[0][h*FF+f]; wB[f] = sW[1][h*FF+f]; }

        float vals[4];
        float mx = -1e30f;
        #pragma unroll
        for (int r = 0; r < 4; r++) {
            const int j = tid + r*256;
            float dw = 0.f, db = 0.f;
            #pragma unroll
            for (int f = 0; f < FF; f++) {
                const float d = sDm[f][j];
                dw = fmaf(d, wW[f], dw);
                db = fmaf(d, wB[f], db);
            }
            const float sp = (dw > 15.f) ? dw : log1pf(__expf(dw));
            const float sc = fmaf(Srow[j], sp, db);
            vals[r] = sc;
            mx = fmaxf(mx, sc);
        }
        mx = blockMax(mx, red);

        float sum = 0.f;
        #pragma unroll
        for (int r = 0; r < 4; r++) {
            vals[r] = __expf(vals[r] - mx);
            sum += vals[r];
        }
        sum = blockSum(sum, red);
        const float inv = 1.f / sum;

        float* Arow = attn + (((size_t)b*HH + h)*LL + i)*LL;
        #pragma unroll
        for (int r = 0; r < 4; r++)
            Arow[tid + r*256] = roundtf(vals[r] * inv);
    }
}

// ============================================================================
// launcher
// ============================================================================
extern "C" void kernel_launch(void* const* d_in, const int* in_sizes, int n_in,
                              void* d_out, int out_size)
{
    const float* q    = (const float*)d_in[0];
    const float* k    = (const float*)d_in[1];
    const float* v    = (const float*)d_in[2];
    const float* dq   = (const float*)d_in[3];
    const float* dkt  = (const float*)d_in[4];
    const float* dkb  = (const float*)d_in[5];
    const float* dks  = (const float*)d_in[6];
    const float* relt = (const float*)d_in[7];
    const float* relb = (const float*)d_in[8];
    const float* W_q  = (const float*)d_in[9];
    const float* b_q  = (const float*)d_in[10];
    const float* W_k  = (const float*)d_in[11];
    const float* W_v  = (const float*)d_in[12];
    // d_in[13] = W_c : unused by the outputs
    const float* W_w  = (const float*)d_in[14];
    const float* W_b  = (const float*)d_in[15];
    const float* W_o  = (const float*)d_in[16];
    const float* b_o  = (const float*)d_in[17];

    float* outO = (float*)d_out;               // [B,L,D]
    float* outA = outO + (size_t)BB*LL*DD;     // [B,H,L,L]

    float *Qp, *Kp, *Vp, *Sp, *AOp;
    float *qr, *kr, *vr, *Wq, *Wk, *Wv, *Wo;
    cudaGetSymbolAddress((void**)&Qp,  g_Q);
    cudaGetSymbolAddress((void**)&Kp,  g_K);
    cudaGetSymbolAddress((void**)&Vp,  g_V);
    cudaGetSymbolAddress((void**)&Sp,  g_S);
    cudaGetSymbolAddress((void**)&AOp, g_AO);
    cudaGetSymbolAddress((void**)&qr,  g_qr);
    cudaGetSymbolAddress((void**)&kr,  g_kr);
    cudaGetSymbolAddress((void**)&vr,  g_vr);
    cudaGetSymbolAddress((void**)&Wq,  g_Wqr);
    cudaGetSymbolAddress((void**)&Wk,  g_Wkr);
    cudaGetSymbolAddress((void**)&Wv,  g_Wvr);
    cudaGetSymbolAddress((void**)&Wo,  g_Wor);

    const int SM_BIG = 3 * (128 + 256) * 36 * 4;   // 165888
    const int SM_AV  = 3 * (256 + 64)  * 36 * 4;   // 138240
    cudaFuncSetAttribute((const void*)mma_gemm<128,256,true>,
                         cudaFuncAttributeMaxDynamicSharedMemorySize, SM_BIG);
    cudaFuncSetAttribute((const void*)mma_gemm<128,256,false>,
                         cudaFuncAttributeMaxDynamicSharedMemorySize, SM_BIG);
    cudaFuncSetAttribute((const void*)mma_gemm<256,64,true>,
                         cudaFuncAttributeMaxDynamicSharedMemorySize, SM_AV);

    // ---- pre-round raw MMA operands to tf32 ----
    {
        const int nIn = BB*LL*DD/4, nW = DD*DD/4;
        round_tf32<<<592, 256>>>((const float4*)q,   (float4*)qr, nIn);
        round_tf32<<<592, 256>>>((const float4*)k,   (float4*)kr, nIn);
        round_tf32<<<592, 256>>>((const float4*)v,   (float4*)vr, nIn);
        round_tf32<<<592, 256>>>((const float4*)W_q, (float4*)Wq, nW);
        round_tf32<<<592, 256>>>((const float4*)W_k, (float4*)Wk, nW);
        round_tf32<<<592, 256>>>((const float4*)W_v, (float4*)Wv, nW);
        round_tf32<<<592, 256>>>((const float4*)W_o, (float4*)Wo, nW);
    }

    // ---- projections: X @ W^T (+bias), outputs rounded for downstream MMA ----
    {
        dim3 grid(DD/256, (BB*LL)/128, 1);
        mma_gemm<128,256,true><<<grid, 256, SM_BIG>>>(qr, Wq, b_q, Qp, DD, DD, DD, DD,
                                                      1, 0,0,0,0,0,0, 1.f);
        mma_gemm<128,256,true><<<grid, 256, SM_BIG>>>(kr, Wk, nullptr, Kp, DD, DD, DD, DD,
                                                      1, 0,0,0,0,0,0, 1.f);
        mma_gemm<128,256,true><<<grid, 256, SM_BIG>>>(vr, Wv, nullptr, Vp, DD, DD, DD, DD,
                                                      1, 0,0,0,0,0,0, 1.f);
    }

    // ---- scores: S[b,h] = (1/8) Qh @ Kh^T (S feeds softmax, no rounding) ----
    {
        dim3 grid(LL/256, LL/128, BB*HH);
        mma_gemm<128,256,false><<<grid, 256, SM_BIG>>>(Qp, Kp, nullptr, Sp, DHH, DD, DD, LL,
            HH, (long long)LL*DD, 64, (long long)LL*DD, 64,
            (long long)HH*LL*LL, (long long)LL*LL, 0.125f);
    }

    // ---- V per-head transpose into g_K (free after scores) ----
    {
        dim3 grid(LL/32, DHH/32, BB*HH);
        transposeV<<<grid, 256>>>(Vp, Kp);
    }

    // ---- distmap bias + softmax -> attn (rounded, direct to d_out) ----
    bias_softmax_kernel<<<BB*LL, 256>>>(
        Sp, dq, dkt, dkb, dks, relt, relb, W_w, W_b, outA);

    // ---- attn @ Vh : M=1024, N=64, K=1024, batch 64 (AO rounded) ----
    {
        dim3 grid(1, LL/256, BB*HH);
        mma_gemm<256,64,true><<<grid, 128, SM_AV>>>(outA, Kp, nullptr, AOp, LL, LL, LL, DD,
            HH, (long long)HH*LL*LL, (long long)LL*LL,
            (long long)HH*DHH*LL, (long long)DHH*LL,
            (long long)LL*DD, 64, 1.f);
    }

    // ---- output projection: AO @ W_o^T + b_o (final, no rounding) ----
    {
        dim3 grid(DD/256, (BB*LL)/128, 1);
        mma_gemm<128,256,false><<<grid, 256, SM_BIG>>>(AOp, Wo, b_o, outO, DD, DD, DD, DD,
                                                       1, 0,0,0,0,0,0, 1.f);
    }
}

// round 6
// speedup vs baseline: 3.5573x; 1.5043x over previous
#include <cuda_runtime.h>
#include <cuda_fp16.h>
#include <cstdint>
#include <math.h>

#define BB  4
#define LL  1024
#define DD  1024
#define HH  16
#define DHH 64
#define FF  7

// ---- scratch (module-static device memory; no runtime allocation) ----
__device__ __align__(16) float  g_S[(size_t)BB*HH*LL*LL];     // raw scores (fp32)
__device__ __align__(16) __half g_attnH[(size_t)BB*HH*LL*LL]; // attn fp16 copy
__device__ __align__(16) __half g_QH[BB*LL*DD];
__device__ __align__(16) __half g_KH[BB*LL*DD];
__device__ __align__(16) __half g_VH[BB*LL*DD];
__device__ __align__(16) __half g_AOH[BB*LL*DD];
// fp16 copies of raw MMA operands
__device__ __align__(16) __half g_qH[BB*LL*DD];
__device__ __align__(16) __half g_kH[BB*LL*DD];
__device__ __align__(16) __half g_vH[BB*LL*DD];
__device__ __align__(16) __half g_WqH[DD*DD];
__device__ __align__(16) __half g_WkH[DD*DD];
__device__ __align__(16) __half g_WvH[DD*DD];
__device__ __align__(16) __half g_WoH[DD*DD];

// ============================================================================
// helpers
// ============================================================================
__device__ __forceinline__ uint32_t smem_u32(const void* p) {
    uint32_t a;
    asm("{ .reg .u64 t; cvta.to.shared.u64 t, %1; cvt.u32.u64 %0, t; }" : "=r"(a) : "l"(p));
    return a;
}
__device__ __forceinline__ void cp16(uint32_t s, const void* g) {
    asm volatile("cp.async.cg.shared.global [%0], [%1], 16;" :: "r"(s), "l"(g) : "memory");
}
#define CP_COMMIT() asm volatile("cp.async.commit_group;" ::: "memory")
#define CP_WAIT1()  asm volatile("cp.async.wait_group 1;" ::: "memory")

#define LDSM4(r0, r1, r2, r3, addr) \
    asm volatile("ldmatrix.sync.aligned.m8n8.x4.shared.b16 {%0,%1,%2,%3}, [%4];" \
        : "=r"(r0), "=r"(r1), "=r"(r2), "=r"(r3) : "r"(addr))

#define MMA_F16(c, a, b) \
    asm volatile("mma.sync.aligned.m16n8k16.row.col.f32.f16.f16.f32 " \
        "{%0,%1,%2,%3}, {%4,%5,%6,%7}, {%8,%9}, {%0,%1,%2,%3};" \
        : "+f"((c)[0]), "+f"((c)[1]), "+f"((c)[2]), "+f"((c)[3]) \
        : "r"((a)[0]), "r"((a)[1]), "r"((a)[2]), "r"((a)[3]), \
          "r"((b)[0]), "r"((b)[1]))

// ============================================================================
// fused fp32 -> fp16 conversion for 7 tensors (blockIdx.y selects tensor)
// ============================================================================
struct CvtArgs {
    const float* src[7];
    __half*      dst[7];
    int          n8[7];   // elements / 8
};

__global__ __launch_bounds__(256)
void cvt_f16(CvtArgs args)
{
    const int t = blockIdx.y;
    const float4* src = (const float4*)args.src[t];
    __half2*      dst = (__half2*)args.dst[t];
    const int n8 = args.n8[t];
    for (int i = blockIdx.x * 256 + threadIdx.x; i < n8; i += gridDim.x * 256) {
        float4 a = src[i * 2], b = src[i * 2 + 1];
        dst[i * 4 + 0] = __floats2half2_rn(a.x, a.y);
        dst[i * 4 + 1] = __floats2half2_rn(a.z, a.w);
        dst[i * 4 + 2] = __floats2half2_rn(b.x, b.y);
        dst[i * 4 + 3] = __floats2half2_rn(b.z, b.w);
    }
}

// ============================================================================
// Tensor-core fp16 GEMM (fp32 accum): C[m,n] = alpha*sum_k A[m,k]*B[n,k] (+bias)
// 64x64 warp tiles; BM x BN block; BK=64 halves (144B padded rows);
// 3-stage cp.async; ldmatrix.b16 fragments. HOUT: emit fp16 C, else fp32.
// ============================================================================
template<int BM, int BN, bool HOUT>
__global__ void __launch_bounds__((BM/64)*(BN/64)*32)
hgemm(const __half* __restrict__ A, const __half* __restrict__ B,
      const float* __restrict__ bias, void* __restrict__ Cv,
      int K, int lda, int ldb, int ldc, int hmod,
      long long aS1, long long aS2, long long bS1, long long bS2,
      long long cS1, long long cS2, float alpha)
{
    constexpr int WARPS_M = BM / 64, WARPS_N = BN / 64;
    constexpr int NTHR = WARPS_M * WARPS_N * 32;
    constexpr int BK = 64;                 // halves per chunk
    constexpr int RB = 144;                // bytes per padded row (128 data + 16 pad)
    constexpr int STB = (BM + BN) * RB;    // bytes per stage
    constexpr int A_IT = BM * 8 / NTHR;
    constexpr int B_IT = BN * 8 / NTHR;
    constexpr int RSTEP = NTHR / 8;
    constexpr int MT = 4, NT = 8;

    extern __shared__ char smc[];

    const int tid = threadIdx.x, lane = tid & 31, wid = tid >> 5;
    const int wm = wid % WARPS_M, wn = wid / WARPS_M;
    const int z = blockIdx.z, zd = z / hmod, zm = z % hmod;
    const __half* Ab = A + zd * aS1 + zm * aS2;
    const __half* Bb = B + zd * bS1 + zm * bS2;
    const int m0 = blockIdx.y * BM, n0 = blockIdx.x * BN;

    // ---- cp.async loader: 8 threads per 128B row ----
    const int lrow = tid >> 3, lq = tid & 7;
    const __half* aG = Ab + (size_t)(m0 + lrow) * lda + lq * 8;
    const __half* bG = Bb + (size_t)(n0 + lrow) * ldb + lq * 8;
    const uint32_t smB = smem_u32(smc);
    const uint32_t aSo = (uint32_t)(lrow * RB + lq * 16);
    const uint32_t bSo = (uint32_t)((BM + lrow) * RB + lq * 16);

    // ---- ldmatrix per-lane addressing ----
    const int mj = lane >> 3, mr = lane & 7;
    const int rowA  = wm * 64 + ((mj & 1) << 3) + mr;    // + mt*16
    const uint32_t kByA = (uint32_t)(mj >> 1) * 16;      // + kk*32
    const int rowB  = BM + wn * 64 + ((mj >> 1) << 3) + mr;  // + p*16
    const uint32_t kByB = (uint32_t)(mj & 1) * 16;

    float acc[MT][NT][4];
    #pragma unroll
    for (int i = 0; i < MT; i++)
        #pragma unroll
        for (int j = 0; j < NT; j++)
            #pragma unroll
            for (int r = 0; r < 4; r++) acc[i][j][r] = 0.f;

    const int NC = K / BK;

    auto LOAD = [&](int c, int s) {
        const uint32_t stb = smB + (uint32_t)s * STB;
        const __half* ap = aG + c * BK;
        const __half* bp = bG + c * BK;
        #pragma unroll
        for (int it = 0; it < A_IT; it++)
            cp16(stb + aSo + (uint32_t)it * RSTEP * RB,
                 ap + (size_t)it * RSTEP * lda);
        #pragma unroll
        for (int it = 0; it < B_IT; it++)
            cp16(stb + bSo + (uint32_t)it * RSTEP * RB,
                 bp + (size_t)it * RSTEP * ldb);
    };

    LOAD(0, 0); CP_COMMIT();
    if (NC > 1) LOAD(1, 1);
    CP_COMMIT();

    for (int c = 0; c < NC; c++) {
        CP_WAIT1();
        __syncthreads();
        if (c + 2 < NC) LOAD(c + 2, (c + 2) % 3);
        CP_COMMIT();

        const uint32_t stb = smB + (uint32_t)(c % 3) * STB;
        #pragma unroll
        for (int kk = 0; kk < 4; kk++) {        // 4 x k16 per 64-half chunk
            uint32_t af[MT][4], bf[NT][2];
            #pragma unroll
            for (int mt = 0; mt < MT; mt++) {
                const uint32_t ad = stb + (uint32_t)(rowA + mt * 16) * RB
                                  + kk * 32 + kByA;
                LDSM4(af[mt][0], af[mt][1], af[mt][2], af[mt][3], ad);
            }
            #pragma unroll
            for (int p = 0; p < 4; p++) {
                const uint32_t bd = stb + (uint32_t)(rowB + p * 16) * RB
                                  + kk * 32 + kByB;
                LDSM4(bf[2*p][0], bf[2*p][1], bf[2*p+1][0], bf[2*p+1][1], bd);
            }
            #pragma unroll
            for (int mt = 0; mt < MT; mt++)
                #pragma unroll
                for (int nt = 0; nt < NT; nt++)
                    MMA_F16(acc[mt][nt], af[mt], bf[nt]);
        }
    }

    // ---- epilogue ----
    #pragma unroll
    for (int mt = 0; mt < MT; mt++) {
        const int m = m0 + wm * 64 + mt * 16 + (lane >> 2);
        #pragma unroll
        for (int nt = 0; nt < NT; nt++) {
            const int n = n0 + wn * 64 + nt * 8 + 2 * (lane & 3);
            float bx = 0.f, by = 0.f;
            if (bias) { bx = bias[n]; by = bias[n + 1]; }
            float2 v0 = { acc[mt][nt][0] * alpha + bx, acc[mt][nt][1] * alpha + by };
            float2 v1 = { acc[mt][nt][2] * alpha + bx, acc[mt][nt][3] * alpha + by };
            if (HOUT) {
                __half* Cb = (__half*)Cv + zd * cS1 + zm * cS2;
                *(__half2*)(Cb + (size_t)m * ldc + n)       = __floats2half2_rn(v0.x, v0.y);
                *(__half2*)(Cb + (size_t)(m + 8) * ldc + n) = __floats2half2_rn(v1.x, v1.y);
            } else {
                float* Cb = (float*)Cv + zd * cS1 + zm * cS2;
                *(float2*)(Cb + (size_t)m * ldc + n)       = v0;
                *(float2*)(Cb + (size_t)(m + 8) * ldc + n) = v1;
            }
        }
    }
}

// ============================================================================
// per-head V transpose (fp16): Vt[(b*H+h)][n][k] = V[b][k][h*64+n]
// ============================================================================
__global__ __launch_bounds__(256)
void transposeV(const __half* __restrict__ V, __half* __restrict__ Vt)
{
    __shared__ __half t[32][34];
    const int z = blockIdx.z;              // b*16+h
    const int b = z >> 4, h = z & 15;
    const int k0 = blockIdx.x * 32, n0 = blockIdx.y * 32;
    const int tx = threadIdx.x & 31, ty = threadIdx.x >> 5;
    #pragma unroll
    for (int i = 0; i < 4; i++)
        t[ty + 8 * i][tx] = V[((size_t)b * LL + k0 + ty + 8 * i) * DD + h * 64 + n0 + tx];
    __syncthreads();
    #pragma unroll
    for (int i = 0; i < 4; i++)
        Vt[((size_t)z * 64 + n0 + ty + 8 * i) * LL + k0 + tx] = t[tx][ty + 8 * i];
}

// ============================================================================
// Bias network + softmax: attn -> fp32 (d_out) + fp16 (scratch for attn@V)
// ============================================================================
__device__ __forceinline__ float blockMax(float v, float* red) {
    #pragma unroll
    for (int o = 16; o; o >>= 1) v = fmaxf(v, __shfl_xor_sync(0xffffffffu, v, o));
    const int w = threadIdx.x >> 5, lane = threadIdx.x & 31;
    __syncthreads();
    if (lane == 0) red[w] = v;
    __syncthreads();
    float r = red[0];
    #pragma unroll
    for (int k = 1; k < 8; k++) r = fmaxf(r, red[k]);
    return r;
}
__device__ __forceinline__ float blockSum(float v, float* red) {
    #pragma unroll
    for (int o = 16; o; o >>= 1) v += __shfl_xor_sync(0xffffffffu, v, o);
    const int w = threadIdx.x >> 5, lane = threadIdx.x & 31;
    __syncthreads();
    if (lane == 0) red[w] = v;
    __syncthreads();
    float r = red[0];
    #pragma unroll
    for (int k = 1; k < 8; k++) r += red[k];
    return r;
}

__global__ __launch_bounds__(256)
void bias_softmax_kernel(const float* __restrict__ S,
                         const float* __restrict__ dq,
                         const float* __restrict__ dkt,
                         const float* __restrict__ dkb,
                         const float* __restrict__ dks,
                         const float* __restrict__ relt,
                         const float* __restrict__ relb,
                         const float* __restrict__ Ww,
                         const float* __restrict__ Wb,
                         float* __restrict__ attn,
                         __half* __restrict__ attnH)
{
    __shared__ float sDm[FF][LL];
    __shared__ float sW[2][HH*FF];
    __shared__ float red[8];

    const int bi  = blockIdx.x;
    const int b   = bi >> 10;
    const int tid = threadIdx.x;

    if (tid < HH*FF) { sW[0][tid] = Ww[tid]; sW[1][tid] = Wb[tid]; }

    const float dq0 = dq[bi*3+0], dq1 = dq[bi*3+1], dq2 = dq[bi*3+2];
    const size_t riBase = (size_t)bi * LL * 4;

    for (int j = tid; j < LL; j += 256) {
        const float* kt = dkt + ((size_t)b*LL + j)*3;
        const float* kb = dkb + ((size_t)b*LL + j)*3;
        const float* ks = dks + ((size_t)b*LL + j)*14;
        const float4 rt = *(const float4*)(relt + riBase + (size_t)j*4);
        const float4 rb = *(const float4*)(relb + riBase + (size_t)j*4);
        float top[FF] = { dq0-kt[0], dq1-kt[1], dq2-kt[2], rt.x, rt.y, rt.z, rt.w };
        float bot[FF] = { dq0-kb[0], dq1-kb[1], dq2-kb[2], rb.x, rb.y, rb.z, rb.w };
        #pragma unroll
        for (int f = 0; f < FF; f++)
            sDm[f][j] = fmaf(top[f], ks[f], bot[f]*ks[7+f]);
    }
    __syncthreads();

    const int i = bi & 1023;
    for (int h = 0; h < HH; h++) {
        const float* Srow = S + (((size_t)b*HH + h)*LL + i)*LL;
        float wW[FF], wB[FF];
        #pragma unroll
        for (int f = 0; f < FF; f++) { wW[f] = sW[0][h*FF+f]; wB[f] = sW[1][h*FF+f]; }

        float vals[4];
        float mx = -1e30f;
        #pragma unroll
        for (int r = 0; r < 4; r++) {
            const int j = tid + r*256;
            float dw = 0.f, db = 0.f;
            #pragma unroll
            for (int f = 0; f < FF; f++) {
                const float d = sDm[f][j];
                dw = fmaf(d, wW[f], dw);
                db = fmaf(d, wB[f], db);
            }
            const float sp = (dw > 15.f) ? dw : log1pf(__expf(dw));
            const float sc = fmaf(Srow[j], sp, db);
            vals[r] = sc;
            mx = fmaxf(mx, sc);
        }
        mx = blockMax(mx, red);

        float sum = 0.f;
        #pragma unroll
        for (int r = 0; r < 4; r++) {
            vals[r] = __expf(vals[r] - mx);
            sum += vals[r];
        }
        sum = blockSum(sum, red);
        const float inv = 1.f / sum;

        const size_t rowOff = (((size_t)b*HH + h)*LL + i)*LL;
        float*  Arow  = attn  + rowOff;
        __half* ArowH = attnH + rowOff;
        #pragma unroll
        for (int r = 0; r < 4; r++) {
            const float a = vals[r] * inv;
            Arow[tid + r*256]  = a;
            ArowH[tid + r*256] = __float2half_rn(a);
        }
    }
}

// ============================================================================
// launcher
// ============================================================================
extern "C" void kernel_launch(void* const* d_in, const int* in_sizes, int n_in,
                              void* d_out, int out_size)
{
    const float* q    = (const float*)d_in[0];
    const float* k    = (const float*)d_in[1];
    const float* v    = (const float*)d_in[2];
    const float* dq   = (const float*)d_in[3];
    const float* dkt  = (const float*)d_in[4];
    const float* dkb  = (const float*)d_in[5];
    const float* dks  = (const float*)d_in[6];
    const float* relt = (const float*)d_in[7];
    const float* relb = (const float*)d_in[8];
    const float* W_q  = (const float*)d_in[9];
    const float* b_q  = (const float*)d_in[10];
    const float* W_k  = (const float*)d_in[11];
    const float* W_v  = (const float*)d_in[12];
    // d_in[13] = W_c : unused by the outputs
    const float* W_w  = (const float*)d_in[14];
    const float* W_b  = (const float*)d_in[15];
    const float* W_o  = (const float*)d_in[16];
    const float* b_o  = (const float*)d_in[17];

    float* outO = (float*)d_out;               // [B,L,D]
    float* outA = outO + (size_t)BB*LL*DD;     // [B,H,L,L]

    float  *Sp;
    __half *QH, *KH, *VH, *AOH, *attnH;
    __half *qH, *kH, *vH, *WqH, *WkH, *WvH, *WoH;
    cudaGetSymbolAddress((void**)&Sp,    g_S);
    cudaGetSymbolAddress((void**)&attnH, g_attnH);
    cudaGetSymbolAddress((void**)&QH,    g_QH);
    cudaGetSymbolAddress((void**)&KH,    g_KH);
    cudaGetSymbolAddress((void**)&VH,    g_VH);
    cudaGetSymbolAddress((void**)&AOH,   g_AOH);
    cudaGetSymbolAddress((void**)&qH,    g_qH);
    cudaGetSymbolAddress((void**)&kH,    g_kH);
    cudaGetSymbolAddress((void**)&vH,    g_vH);
    cudaGetSymbolAddress((void**)&WqH,   g_WqH);
    cudaGetSymbolAddress((void**)&WkH,   g_WkH);
    cudaGetSymbolAddress((void**)&WvH,   g_WvH);
    cudaGetSymbolAddress((void**)&WoH,   g_WoH);

    const int SM_BIG = 3 * (128 + 256) * 144;   // 165888
    const int SM_AV  = 3 * (256 + 64)  * 144;   // 138240
    cudaFuncSetAttribute((const void*)hgemm<128,256,true>,
                         cudaFuncAttributeMaxDynamicSharedMemorySize, SM_BIG);
    cudaFuncSetAttribute((const void*)hgemm<128,256,false>,
                         cudaFuncAttributeMaxDynamicSharedMemorySize, SM_BIG);
    cudaFuncSetAttribute((const void*)hgemm<256,64,true>,
                         cudaFuncAttributeMaxDynamicSharedMemorySize, SM_AV);

    // ---- fused fp32 -> fp16 conversion of raw MMA operands ----
    {
        CvtArgs a;
        a.src[0] = q;   a.dst[0] = qH;  a.n8[0] = BB*LL*DD/8;
        a.src[1] = k;   a.dst[1] = kH;  a.n8[1] = BB*LL*DD/8;
        a.src[2] = v;   a.dst[2] = vH;  a.n8[2] = BB*LL*DD/8;
        a.src[3] = W_q; a.dst[3] = WqH; a.n8[3] = DD*DD/8;
        a.src[4] = W_k; a.dst[4] = WkH; a.n8[4] = DD*DD/8;
        a.src[5] = W_v; a.dst[5] = WvH; a.n8[5] = DD*DD/8;
        a.src[6] = W_o; a.dst[6] = WoH; a.n8[6] = DD*DD/8;
        dim3 grid(148, 7, 1);
        cvt_f16<<<grid, 256>>>(a);
    }

    // ---- projections: X @ W^T (+bias), fp16 out ----
    {
        dim3 grid(DD/256, (BB*LL)/128, 1);
        hgemm<128,256,true><<<grid, 256, SM_BIG>>>(qH, WqH, b_q, QH, DD, DD, DD, DD,
                                                   1, 0,0,0,0,0,0, 1.f);
        hgemm<128,256,true><<<grid, 256, SM_BIG>>>(kH, WkH, nullptr, KH, DD, DD, DD, DD,
                                                   1, 0,0,0,0,0,0, 1.f);
        hgemm<128,256,true><<<grid, 256, SM_BIG>>>(vH, WvH, nullptr, VH, DD, DD, DD, DD,
                                                   1, 0,0,0,0,0,0, 1.f);
    }

    // ---- scores: S[b,h] = (1/8) Qh @ Kh^T (fp32 out), K=64 -> single chunk ----
    {
        dim3 grid(LL/256, LL/128, BB*HH);
        hgemm<128,256,false><<<grid, 256, SM_BIG>>>(QH, KH, nullptr, Sp, DHH, DD, DD, LL,
            HH, (long long)LL*DD, 64, (long long)LL*DD, 64,
            (long long)HH*LL*LL, (long long)LL*LL, 0.125f);
    }

    // ---- V per-head transpose into g_QH (free after scores) ----
    {
        dim3 grid(LL/32, DHH/32, BB*HH);
        transposeV<<<grid, 256>>>(VH, QH);
    }

    // ---- distmap bias + softmax -> attn fp32 (d_out) + fp16 (scratch) ----
    bias_softmax_kernel<<<BB*LL, 256>>>(
        Sp, dq, dkt, dkb, dks, relt, relb, W_w, W_b, outA, attnH);

    // ---- attn @ Vh : M=1024, N=64, K=1024, batch 64, fp16 out ----
    {
        dim3 grid(1, LL/256, BB*HH);
        hgemm<256,64,true><<<grid, 128, SM_AV>>>(attnH, QH, nullptr, AOH, LL, LL, LL, DD,
            HH, (long long)HH*LL*LL, (long long)LL*LL,
            (long long)HH*DHH*LL, (long long)DHH*LL,
            (long long)LL*DD, 64, 1.f);
    }

    // ---- output projection: AO @ W_o^T + b_o (fp32 out) ----
    {
        dim3 grid(DD/256, (BB*LL)/128, 1);
        hgemm<128,256,false><<<grid, 256, SM_BIG>>>(AOH, WoH, b_o, outO, DD, DD, DD, DD,
                                                    1, 0,0,0,0,0,0, 1.f);
    }
}